// round 2
// baseline (speedup 1.0000x reference)
#include <cuda_runtime.h>
#include <cuda_bf16.h>

#define HH 256
#define WW 256
#define NMASK 64
#define CDIM 81
#define BQ 200
#define HW (HH*WW)

// Global accumulators (no device mallocs allowed).
// g_acc: 0 = ce weighted-nll sum, 1 = ce weight sum, 2 = pairwise sim*tgt sum, 3 = tgt count
__device__ double g_acc[4];
__device__ double g_projx[NMASK * 3];  // per-n: sum ix*tx, sum ix^2, sum tx^2
__device__ double g_projy[NMASK * 3];  // per-n: sum iy*ty, sum iy^2, sum ty^2

// ---------------------------------------------------------------------------
__global__ void init_kernel() {
    int i = threadIdx.x;
    if (i < 4) g_acc[i] = 0.0;
    if (i < NMASK * 3) { g_projx[i] = 0.0; g_projy[i] = 0.0; }
}

// ---------------------------------------------------------------------------
// Cross-entropy: one block, thread t handles row t (t < 200).
__global__ void ce_kernel(const float* __restrict__ logits,
                          const int* __restrict__ cls,
                          const float* __restrict__ ew) {
    int row = threadIdx.x;
    float wn = 0.f, wv = 0.f;
    if (row < BQ) {
        const float* p = logits + row * CDIM;
        float mx = -1e30f;
        #pragma unroll 4
        for (int c = 0; c < CDIM; c++) mx = fmaxf(mx, p[c]);
        float se = 0.f;
        #pragma unroll 4
        for (int c = 0; c < CDIM; c++) se += __expf(p[c] - mx);
        int t = cls[row];
        float logp = p[t] - mx - __logf(se);
        float w = ew[t];
        wn = -w * logp;
        wv = w;
    }
    // block reduce (256 threads)
    __shared__ float s1[256], s2[256];
    int tid = threadIdx.x;
    s1[tid] = wn; s2[tid] = wv;
    __syncthreads();
    for (int o = 128; o > 0; o >>= 1) {
        if (tid < o) { s1[tid] += s1[tid + o]; s2[tid] += s2[tid + o]; }
        __syncthreads();
    }
    if (tid == 0) { g_acc[0] = (double)s1[0]; g_acc[1] = (double)s2[0]; }
}

// ---------------------------------------------------------------------------
// Pairwise loss. sim = sp(xc) + sp(xn) - sp(xc+xn), sp = softplus (exact
// identity with logaddexp(lfg_c+lfg_n, lbg_c+lbg_n) negated).
// OOB neighbors (zero-padded log-sig images) give sim == 0 exactly -> skipped,
// but tgt = (ts >= 0.3)*box is still counted.
__device__ __forceinline__ float softplusf(float z) {
    return fmaxf(z, 0.f) + log1pf(__expf(-fabsf(z)));
}

__global__ void pair_kernel(const float* __restrict__ src,
                            const float* __restrict__ sims,
                            const int* __restrict__ box) {
    const int n = blockIdx.z;
    const int h0 = blockIdx.y * 8;
    const int w0 = blockIdx.x * 32;

    __shared__ float sx[12][36];   // x values, 2-pixel halo
    __shared__ float ssp[12][36];  // softplus(x)

    const int tid = threadIdx.y * 32 + threadIdx.x;
    const float* srcn = src + (size_t)n * HW;

    for (int idx = tid; idx < 12 * 36; idx += 256) {
        int r = idx / 36, c = idx % 36;
        int gh = h0 - 2 + r, gw = w0 - 2 + c;
        float x = 0.f;
        if ((unsigned)gh < HH && (unsigned)gw < WW) x = srcn[gh * WW + gw];
        sx[r][c] = x;
        ssp[r][c] = softplusf(x);
    }
    __syncthreads();

    const int h = h0 + threadIdx.y;
    const int w = w0 + threadIdx.x;

    float sum = 0.f, cnt = 0.f;
    const int b = box[(size_t)n * HW + h * WW + w];
    if (b) {
        const int ly = threadIdx.y + 2, lx = threadIdx.x + 2;
        const float xc = sx[ly][lx];
        const float spc = ssp[ly][lx];
        const int di[8] = {-2, -2, -2, 0, 0, 2, 2, 2};
        const int dj[8] = {-2, 0, 2, -2, 2, -2, 0, 2};
        const float* simn = sims + (size_t)n * 8 * HW + h * WW + w;
        #pragma unroll
        for (int p = 0; p < 8; p++) {
            float ts = simn[(size_t)p * HW];
            if (ts >= 0.3f) {
                cnt += 1.f;
                int nh = h + di[p], nw = w + dj[p];
                if ((unsigned)nh < HH && (unsigned)nw < WW) {
                    float xn = sx[ly + di[p]][lx + dj[p]];
                    float spn = ssp[ly + di[p]][lx + dj[p]];
                    sum += spc + spn - softplusf(xc + xn);
                }
            }
        }
    }

    // warp reduce then block reduce
    #pragma unroll
    for (int o = 16; o > 0; o >>= 1) {
        sum += __shfl_down_sync(0xffffffff, sum, o);
        cnt += __shfl_down_sync(0xffffffff, cnt, o);
    }
    __shared__ float rs[8], rc[8];
    int wid = tid >> 5, lane = tid & 31;
    if (lane == 0) { rs[wid] = sum; rc[wid] = cnt; }
    __syncthreads();
    if (tid == 0) {
        float S = 0.f, C = 0.f;
        #pragma unroll
        for (int i = 0; i < 8; i++) { S += rs[i]; C += rc[i]; }
        atomicAdd(&g_acc[2], (double)S);
        atomicAdd(&g_acc[3], (double)C);
    }
}

// ---------------------------------------------------------------------------
// Row maxes (over w): ix = sigmoid(max_w src), tx = max_w box. One warp per h.
__global__ void projrow_kernel(const float* __restrict__ src,
                               const int* __restrict__ box) {
    const int n = blockIdx.y;
    const int h = blockIdx.x * 8 + (threadIdx.x >> 5);
    const int lane = threadIdx.x & 31;
    const float* p = src + ((size_t)n * HH + h) * WW;
    const int* bp = box + ((size_t)n * HH + h) * WW;
    float m = -1e30f; int bm = 0;
    #pragma unroll
    for (int k = 0; k < 8; k++) {
        int w = lane + k * 32;
        m = fmaxf(m, p[w]);
        bm = max(bm, bp[w]);
    }
    #pragma unroll
    for (int o = 16; o > 0; o >>= 1) {
        m = fmaxf(m, __shfl_xor_sync(0xffffffff, m, o));
        bm = max(bm, __shfl_xor_sync(0xffffffff, bm, o));
    }
    if (lane == 0) {
        float ix = 1.f / (1.f + __expf(-m));
        float tx = (float)bm;
        atomicAdd(&g_projx[n * 3 + 0], (double)(ix * tx));
        atomicAdd(&g_projx[n * 3 + 1], (double)(ix * ix));
        atomicAdd(&g_projx[n * 3 + 2], (double)(tx * tx));
    }
}

// Column maxes (over h): one block per n, thread = w, coalesced h loop.
__global__ void projcol_kernel(const float* __restrict__ src,
                               const int* __restrict__ box) {
    const int n = blockIdx.x;
    const int w = threadIdx.x;
    const float* p = src + (size_t)n * HW + w;
    const int* bp = box + (size_t)n * HW + w;
    float m = -1e30f; int bm = 0;
    #pragma unroll 4
    for (int hh = 0; hh < HH; hh++) {
        m = fmaxf(m, p[hh * WW]);
        bm = max(bm, bp[hh * WW]);
    }
    float iy = 1.f / (1.f + __expf(-m));
    float ty = (float)bm;
    float a0 = iy * ty, a1 = iy * iy, a2 = ty * ty;
    #pragma unroll
    for (int o = 16; o > 0; o >>= 1) {
        a0 += __shfl_down_sync(0xffffffff, a0, o);
        a1 += __shfl_down_sync(0xffffffff, a1, o);
        a2 += __shfl_down_sync(0xffffffff, a2, o);
    }
    __shared__ float r0[8], r1[8], r2[8];
    int wid = w >> 5, lane = w & 31;
    if (lane == 0) { r0[wid] = a0; r1[wid] = a1; r2[wid] = a2; }
    __syncthreads();
    if (w == 0) {
        float s0 = 0.f, s1 = 0.f, s2 = 0.f;
        #pragma unroll
        for (int i = 0; i < 8; i++) { s0 += r0[i]; s1 += r1[i]; s2 += r2[i]; }
        g_projy[n * 3 + 0] = (double)s0;
        g_projy[n * 3 + 1] = (double)s1;
        g_projy[n * 3 + 2] = (double)s2;
    }
}

// ---------------------------------------------------------------------------
__global__ void final_kernel(const int* __restrict__ num_masks_p,
                             float* __restrict__ out) {
    int v = num_masks_p[0];
    // Defensive: if the scalar arrived as float32 bits, reinterpret.
    if (v <= 0 || v > 1000000) {
        float f = __int_as_float(v);
        v = (int)f;
    }
    double nm = (double)max(v, 1);
    double ce = g_acc[0] / g_acc[1];
    double pair = g_acc[2] / fmax(g_acc[3], 1.0) / nm;
    double proj = 0.0;
    for (int n = 0; n < NMASK; n++) {
        double lx = 1.0 - 2.0 * g_projx[n * 3] /
                          (g_projx[n * 3 + 1] + g_projx[n * 3 + 2] + 1e-3);
        double ly = 1.0 - 2.0 * g_projy[n * 3] /
                          (g_projy[n * 3 + 1] + g_projy[n * 3 + 2] + 1e-3);
        proj += lx + ly;
    }
    proj /= nm;
    out[0] = (float)(ce + pair + proj);
}

// ---------------------------------------------------------------------------
extern "C" void kernel_launch(void* const* d_in, const int* in_sizes, int n_in,
                              void* d_out, int out_size) {
    const float* pred_logits = (const float*)d_in[0];   // (2,100,81)
    const float* src_masks   = (const float*)d_in[1];   // (64,256,256)
    const float* empty_w     = (const float*)d_in[2];   // (81,)
    const float* sims        = (const float*)d_in[3];   // (64,8,256,256)
    const int*   tgt_cls     = (const int*)d_in[4];     // (2,100)
    const int*   box         = (const int*)d_in[5];     // (64,256,256)
    const int*   num_masks   = (const int*)d_in[6];     // scalar
    float* out = (float*)d_out;

    init_kernel<<<1, 256>>>();
    ce_kernel<<<1, 256>>>(pred_logits, tgt_cls, empty_w);

    dim3 pb(32, 8);
    dim3 pg(WW / 32, HH / 8, NMASK);
    pair_kernel<<<pg, pb>>>(src_masks, sims, box);

    projrow_kernel<<<dim3(HH / 8, NMASK), 256>>>(src_masks, box);
    projcol_kernel<<<NMASK, 256>>>(src_masks, box);

    final_kernel<<<1, 1>>>(num_masks, out);
}

// round 3
// speedup vs baseline: 1.2937x; 1.2937x over previous
#include <cuda_runtime.h>
#include <cuda_bf16.h>

#define HH 256
#define WW 256
#define NMASK 64
#define CDIM 81
#define BQ 200
#define HW (HH*WW)

// Accumulators (device globals; no mallocs allowed).
__device__ double g_acc[4];             // 0: ce wnll, 1: ce wsum, 2: pair sum, 3: tgt cnt
__device__ double g_projx[NMASK * 3];
__device__ double g_projy[NMASK * 3];
__device__ unsigned g_rowmax[NMASK * HH];  // fp32 order-encoded max of src over w
__device__ unsigned g_colmax[NMASK * WW];  // ... over h
__device__ int g_rowbox[NMASK * HH];
__device__ int g_colbox[NMASK * WW];

__device__ __forceinline__ unsigned fenc(float f) {
    unsigned u = __float_as_uint(f);
    return (u & 0x80000000u) ? ~u : (u | 0x80000000u);
}
__device__ __forceinline__ float fdec(unsigned u) {
    return (u & 0x80000000u) ? __uint_as_float(u & 0x7fffffffu) : __uint_as_float(~u);
}
__device__ __forceinline__ float softplusf(float z) {
    return fmaxf(z, 0.f) + log1pf(__expf(-fabsf(z)));
}

// ---------------------------------------------------------------------------
__global__ void init_kernel() {
    int i = blockIdx.x * blockDim.x + threadIdx.x;
    if (i < 4) g_acc[i] = 0.0;
    if (i < NMASK * 3) { g_projx[i] = 0.0; g_projy[i] = 0.0; }
    if (i < NMASK * HH) {
        g_rowmax[i] = 0u; g_rowbox[i] = 0;
        g_colmax[i] = 0u; g_colbox[i] = 0;
    }
}

// ---------------------------------------------------------------------------
__global__ void ce_kernel(const float* __restrict__ logits,
                          const int* __restrict__ cls,
                          const float* __restrict__ ew) {
    int row = threadIdx.x;
    float wn = 0.f, wv = 0.f;
    if (row < BQ) {
        const float* p = logits + row * CDIM;
        float mx = -1e30f;
        #pragma unroll 4
        for (int c = 0; c < CDIM; c++) mx = fmaxf(mx, p[c]);
        float se = 0.f;
        #pragma unroll 4
        for (int c = 0; c < CDIM; c++) se += __expf(p[c] - mx);
        int t = cls[row];
        float logp = p[t] - mx - __logf(se);
        float w = ew[t];
        wn = -w * logp;
        wv = w;
    }
    __shared__ float s1[256], s2[256];
    int tid = threadIdx.x;
    s1[tid] = wn; s2[tid] = wv;
    __syncthreads();
    for (int o = 128; o > 0; o >>= 1) {
        if (tid < o) { s1[tid] += s1[tid + o]; s2[tid] += s2[tid + o]; }
        __syncthreads();
    }
    if (tid == 0) { g_acc[0] = (double)s1[0]; g_acc[1] = (double)s2[0]; }
}

// ---------------------------------------------------------------------------
// Fused pairwise + projection-max pass.
// Tile: 128 wide x 8 high per block (256 threads, 4 px/thread, float4 loads).
// sim = sp(xc) + sp(xn) - sp(xc+xn); OOB neighbors contribute exactly 0.
__global__ __launch_bounds__(256)
void pair_kernel(const float* __restrict__ src,
                 const float* __restrict__ sims,
                 const int* __restrict__ box) {
    const int n = blockIdx.z;
    const int h0 = blockIdx.y * 8;
    const int w0 = blockIdx.x * 128;
    const int tx = threadIdx.x;       // 0..31
    const int ty = threadIdx.y;       // 0..7
    const int tid = ty * 32 + tx;

    __shared__ float sx[12][132];     // src values, 2-px halo
    __shared__ float ssp[12][132];    // softplus(src)
    __shared__ int   sb[8][128];      // box tile

    const int h = h0 + ty;
    const int wbase = w0 + tx * 4;

    // Front-batched wide loads: 8 sims planes + box, all independent.
    float4 sv[8];
    const float* simp = sims + (size_t)n * 8 * HW + h * WW + wbase;
    #pragma unroll
    for (int p = 0; p < 8; p++)
        sv[p] = __ldcs((const float4*)(simp + (size_t)p * HW));
    int4 b4 = *(const int4*)(box + (size_t)n * HW + h * WW + wbase);

    // Fill shared src tile (+ halo) and softplus.
    const float* srcn = src + (size_t)n * HW;
    for (int idx = tid; idx < 12 * 132; idx += 256) {
        int r = idx / 132, c = idx - r * 132;
        int gh = h0 - 2 + r, gw = w0 - 2 + c;
        float x = 0.f;
        if ((unsigned)gh < HH && (unsigned)gw < WW) x = srcn[gh * WW + gw];
        sx[r][c] = x;
        ssp[r][c] = softplusf(x);
    }
    sb[ty][tx * 4 + 0] = b4.x;
    sb[ty][tx * 4 + 1] = b4.y;
    sb[ty][tx * 4 + 2] = b4.z;
    sb[ty][tx * 4 + 3] = b4.w;
    __syncthreads();

    const int di[8] = {-2, -2, -2, 0, 0, 2, 2, 2};
    const int dj[8] = {-2, 0, 2, -2, 2, -2, 0, 2};
    const float* svp = (const float*)sv;
    const int* bp = (const int*)&b4;

    float sum = 0.f, cnt = 0.f;
    float rmax = -1e30f;
    int rbox = 0;

    #pragma unroll
    for (int i = 0; i < 4; i++) {
        const int lx = tx * 4 + i + 2, ly = ty + 2;
        const float xc = sx[ly][lx];
        rmax = fmaxf(rmax, xc);
        const int b = bp[i];
        rbox |= b;
        if (b) {
            const float spc = ssp[ly][lx];
            const int w = wbase + i;
            #pragma unroll
            for (int p = 0; p < 8; p++) {
                float ts = svp[p * 4 + i];
                if (ts >= 0.3f) {
                    cnt += 1.f;
                    int nh = h + di[p], nw = w + dj[p];
                    if ((unsigned)nh < HH && (unsigned)nw < WW) {
                        float xn = sx[ly + di[p]][lx + dj[p]];
                        sum += spc + ssp[ly + di[p]][lx + dj[p]] - softplusf(xc + xn);
                    }
                }
            }
        }
    }

    // Per-row (warp) reduce: pairwise sums + row max/box.
    #pragma unroll
    for (int o = 16; o > 0; o >>= 1) {
        sum += __shfl_down_sync(0xffffffff, sum, o);
        cnt += __shfl_down_sync(0xffffffff, cnt, o);
        rmax = fmaxf(rmax, __shfl_xor_sync(0xffffffff, rmax, o));
        rbox |= __shfl_xor_sync(0xffffffff, rbox, o);
    }
    if (tx == 0) {
        atomicMax(&g_rowmax[n * HH + h], fenc(rmax));
        if (rbox) g_rowbox[n * HH + h] = 1;   // idempotent store
    }

    // Column partials from the shared tile (threads 0..127, one column each).
    if (tid < 128) {
        const int c = tid;
        float m = -1e30f; int ob = 0;
        #pragma unroll
        for (int r = 0; r < 8; r++) {
            m = fmaxf(m, sx[r + 2][c + 2]);
            ob |= sb[r][c];
        }
        atomicMax(&g_colmax[n * WW + w0 + c], fenc(m));
        if (ob) g_colbox[n * WW + w0 + c] = 1;
    }

    // Block reduce pairwise sums -> one double atomic each.
    __shared__ float rs[8], rc[8];
    if (tx == 0) { rs[ty] = sum; rc[ty] = cnt; }
    __syncthreads();
    if (tid == 0) {
        float S = 0.f, C = 0.f;
        #pragma unroll
        for (int i = 0; i < 8; i++) { S += rs[i]; C += rc[i]; }
        atomicAdd(&g_acc[2], (double)S);
        atomicAdd(&g_acc[3], (double)C);
    }
}

// ---------------------------------------------------------------------------
// Finish projection losses from the 64x256 max arrays. One block per n.
__global__ void projfinish_kernel() {
    const int n = blockIdx.x;
    const int t = threadIdx.x;   // 0..255

    float mr = fdec(g_rowmax[n * HH + t]);
    float ix = 1.f / (1.f + __expf(-mr));
    float txv = (float)g_rowbox[n * HH + t];
    float a0 = ix * txv, a1 = ix * ix, a2 = txv * txv;

    float mc = fdec(g_colmax[n * WW + t]);
    float iy = 1.f / (1.f + __expf(-mc));
    float tyv = (float)g_colbox[n * WW + t];
    float b0 = iy * tyv, b1 = iy * iy, b2 = tyv * tyv;

    #pragma unroll
    for (int o = 16; o > 0; o >>= 1) {
        a0 += __shfl_down_sync(0xffffffff, a0, o);
        a1 += __shfl_down_sync(0xffffffff, a1, o);
        a2 += __shfl_down_sync(0xffffffff, a2, o);
        b0 += __shfl_down_sync(0xffffffff, b0, o);
        b1 += __shfl_down_sync(0xffffffff, b1, o);
        b2 += __shfl_down_sync(0xffffffff, b2, o);
    }
    __shared__ float r[6][8];
    int wid = t >> 5, lane = t & 31;
    if (lane == 0) {
        r[0][wid] = a0; r[1][wid] = a1; r[2][wid] = a2;
        r[3][wid] = b0; r[4][wid] = b1; r[5][wid] = b2;
    }
    __syncthreads();
    if (t == 0) {
        float s[6] = {0, 0, 0, 0, 0, 0};
        #pragma unroll
        for (int i = 0; i < 8; i++)
            #pragma unroll
            for (int k = 0; k < 6; k++) s[k] += r[k][i];
        g_projx[n * 3 + 0] = (double)s[0];
        g_projx[n * 3 + 1] = (double)s[1];
        g_projx[n * 3 + 2] = (double)s[2];
        g_projy[n * 3 + 0] = (double)s[3];
        g_projy[n * 3 + 1] = (double)s[4];
        g_projy[n * 3 + 2] = (double)s[5];
    }
}

// ---------------------------------------------------------------------------
__global__ void final_kernel(const int* __restrict__ num_masks_p,
                             float* __restrict__ out) {
    int v = num_masks_p[0];
    if (v <= 0 || v > 1000000) {
        float f = __int_as_float(v);
        v = (int)f;
    }
    double nm = (double)max(v, 1);
    double ce = g_acc[0] / g_acc[1];
    double pair = g_acc[2] / fmax(g_acc[3], 1.0) / nm;
    double proj = 0.0;
    for (int n = 0; n < NMASK; n++) {
        double lx = 1.0 - 2.0 * g_projx[n * 3] /
                          (g_projx[n * 3 + 1] + g_projx[n * 3 + 2] + 1e-3);
        double ly = 1.0 - 2.0 * g_projy[n * 3] /
                          (g_projy[n * 3 + 1] + g_projy[n * 3 + 2] + 1e-3);
        proj += lx + ly;
    }
    proj /= nm;
    out[0] = (float)(ce + pair + proj);
}

// ---------------------------------------------------------------------------
extern "C" void kernel_launch(void* const* d_in, const int* in_sizes, int n_in,
                              void* d_out, int out_size) {
    const float* pred_logits = (const float*)d_in[0];   // (2,100,81)
    const float* src_masks   = (const float*)d_in[1];   // (64,256,256)
    const float* empty_w     = (const float*)d_in[2];   // (81,)
    const float* sims        = (const float*)d_in[3];   // (64,8,256,256)
    const int*   tgt_cls     = (const int*)d_in[4];     // (2,100)
    const int*   box         = (const int*)d_in[5];     // (64,256,256)
    const int*   num_masks   = (const int*)d_in[6];     // scalar
    float* out = (float*)d_out;

    init_kernel<<<64, 256>>>();
    ce_kernel<<<1, 256>>>(pred_logits, tgt_cls, empty_w);

    pair_kernel<<<dim3(WW / 128, HH / 8, NMASK), dim3(32, 8)>>>(src_masks, sims, box);

    projfinish_kernel<<<NMASK, 256>>>();
    final_kernel<<<1, 1>>>(num_masks, out);
}